// round 5
// baseline (speedup 1.0000x reference)
#include <cuda_runtime.h>
#include <math.h>

#define FULL 0xffffffffu
typedef unsigned long long u64;

// Scratch token buffer: (B=16, T=128, slots=67, EMBED=32) fp32
__device__ float g_tokens[16 * 128 * 67 * 32];

__device__ __forceinline__ float warp_sum(float v) {
    v += __shfl_xor_sync(FULL, v, 16);
    v += __shfl_xor_sync(FULL, v, 8);
    v += __shfl_xor_sync(FULL, v, 4);
    v += __shfl_xor_sync(FULL, v, 2);
    v += __shfl_xor_sync(FULL, v, 1);
    return v;
}

// ---- packed f32x2 helpers ----
__device__ __forceinline__ u64 fma2(u64 a, u64 b, u64 c) {
    u64 d; asm("fma.rn.f32x2 %0, %1, %2, %3;" : "=l"(d) : "l"(a), "l"(b), "l"(c)); return d;
}
__device__ __forceinline__ u64 mul2(u64 a, u64 b) {
    u64 d; asm("mul.rn.f32x2 %0, %1, %2;" : "=l"(d) : "l"(a), "l"(b)); return d;
}
__device__ __forceinline__ u64 add2(u64 a, u64 b) {
    u64 d; asm("add.rn.f32x2 %0, %1, %2;" : "=l"(d) : "l"(a), "l"(b)); return d;
}
__device__ __forceinline__ u64 pack2(float lo, float hi) {
    u64 d; asm("mov.b64 %0, {%1, %2};" : "=l"(d) : "f"(lo), "f"(hi)); return d;
}
__device__ __forceinline__ float hsum2(u64 v) {
    float lo, hi; asm("mov.b64 {%0, %1}, %2;" : "=f"(lo), "=f"(hi) : "l"(v)); return lo + hi;
}

__device__ __forceinline__ void ld_row16(u64* r, const float* p) {
    const ulonglong2* q = (const ulonglong2*)p;
#pragma unroll
    for (int i = 0; i < 8; i++) { ulonglong2 t = q[i]; r[2 * i] = t.x; r[2 * i + 1] = t.y; }
}

__device__ __forceinline__ float dot32(const float* wrow, const u64* v2) {
    const ulonglong2* w = (const ulonglong2*)wrow;
    ulonglong2 t0 = w[0], t1 = w[1];
    u64 a0 = mul2(v2[0], t0.x); a0 = fma2(v2[1], t0.y, a0);
    u64 a1 = mul2(v2[2], t1.x); a1 = fma2(v2[3], t1.y, a1);
#pragma unroll
    for (int i = 2; i < 8; i += 2) {
        ulonglong2 u0 = w[i], u1 = w[i + 1];
        a0 = fma2(v2[2 * i], u0.x, a0);
        a0 = fma2(v2[2 * i + 1], u0.y, a0);
        a1 = fma2(v2[2 * i + 2], u1.x, a1);
        a1 = fma2(v2[2 * i + 3], u1.y, a1);
    }
    return hsum2(add2(a0, a1));
}

__device__ __forceinline__ float sumsq16(const u64* v) {
    u64 a0 = mul2(v[0], v[0]);
    u64 a1 = mul2(v[1], v[1]);
#pragma unroll
    for (int i = 2; i < 16; i += 2) {
        a0 = fma2(v[i], v[i], a0);
        a1 = fma2(v[i + 1], v[i + 1], a1);
    }
    return hsum2(add2(a0, a1));
}

// ---------------------------------------------------------------------------
// Kernel 0: tokenize + input rmsnorm. grid = B*T (2048), block = 256.
// ---------------------------------------------------------------------------
__global__ void embed_kernel(const float* __restrict__ obs,
                             const float* __restrict__ Wval,
                             const float* __restrict__ bval,
                             const float* __restrict__ innorm,
                             const float* __restrict__ dimemb,
                             const float* __restrict__ cls) {
    int bt = blockIdx.x;
    int tid = threadIdx.x;
    int wid = tid >> 5, lane = tid & 31;
    for (int s = wid; s < 67; s += 8) {
        float val;
        if (s < 64)
            val = fmaf(obs[bt * 64 + s], Wval[lane], bval[lane]) + dimemb[s * 32 + lane];
        else
            val = cls[(s - 64) * 32 + lane];
        float ms = warp_sum(val * val) * (1.f / 32.f);
        g_tokens[(bt * 67 + s) * 32 + lane] = val * rsqrtf(ms + 1e-6f) * innorm[lane];
    }
}

// ---------------------------------------------------------------------------
// Token-per-lane fused block with coalesced gmem staging through smem.
// Per-seq smem layout: [x rows | K rows | V rows], each S x 36 floats.
// x area doubles as output staging (own-row exclusivity, no extra syncs).
// ---------------------------------------------------------------------------
template <int S, int NSEQ, bool TEMPORAL>
__global__ void __launch_bounds__(32 * ((S * NSEQ + 31) / 32))
attn_tpl(const float* __restrict__ Wq, const float* __restrict__ Wk,
         const float* __restrict__ Wv, const float* __restrict__ Wo,
         const float* __restrict__ Wg, const float* __restrict__ Wu,
         const float* __restrict__ Wout, const float* __restrict__ norm4,
         const float* __restrict__ qkn, int nseq_total) {
    constexpr int BLK = 32 * ((S * NSEQ + 31) / 32);
    constexpr int ROW = 36;
    constexpr int SEQSTR = 3 * S * ROW;     // x,k,v areas per sequence
    constexpr int DATSZ = NSEQ * SEQSTR;

    extern __shared__ float sm[];
    float* sdat  = sm;                 // DATSZ
    float* swq   = sdat + DATSZ;       // 1024
    float* swk   = swq + 1024;
    float* swv   = swk + 1024;
    float* swo   = swv + 1024;
    float* swg   = swo + 1024;         // 2048
    float* swu   = swg + 2048;         // 2048
    float* swout = swu + 2048;         // 2048 transposed [f][d]
    float* snorm = swout + 2048;       // 128
    float* sqkn  = snorm + 128;        // 16

    const int tid = threadIdx.x;
    int gseq0 = blockIdx.x * NSEQ;
    int nvalid = (min(gseq0 + NSEQ, nseq_total) - gseq0) * S;

    // ---- stage weights ----
    for (int i = tid; i < 256; i += BLK) {
        ((float4*)swq)[i] = ((const float4*)Wq)[i];
        ((float4*)swk)[i] = ((const float4*)Wk)[i];
        ((float4*)swv)[i] = ((const float4*)Wv)[i];
        ((float4*)swo)[i] = ((const float4*)Wo)[i];
    }
    for (int i = tid; i < 512; i += BLK) {
        ((float4*)swg)[i] = ((const float4*)Wg)[i];
        ((float4*)swu)[i] = ((const float4*)Wu)[i];
    }
    for (int i = tid; i < 2048; i += BLK) {   // transpose Wout -> [f][d]
        int f = i >> 5, d = i & 31;
        swout[i] = Wout[d * 64 + f];
    }
    if (tid < 32) ((float4*)snorm)[tid] = ((const float4*)norm4)[tid];
    if (tid < 4) ((float4*)sqkn)[tid] = ((const float4*)qkn)[tid];

    // ---- stage x: coalesced gmem -> smem x-areas ----
    for (int i = tid; i < nvalid * 8; i += BLK) {
        int token = i >> 3, part = i & 7;
        int seq = token / S, t = token - seq * S;
        const float* src;
        if (TEMPORAL) {
            int gs = gseq0 + seq;
            int b = gs / 67, sl = gs - b * 67;
            src = g_tokens + ((long)(b * 128 + t) * 67 + sl) * 32 + 4 * part;
        } else {
            src = g_tokens + (long)gseq0 * (67 * 32) + (long)i * 4;
        }
        *(float4*)(sdat + seq * SEQSTR + t * ROW + 4 * part) = *(const float4*)src;
    }
    __syncthreads();

    // ---- per-lane token assignment ----
    bool valid = tid < nvalid;
    int tcl = valid ? tid : (nvalid - 1);
    int seq = tcl / S;
    int tok = tcl - seq * S;

    float* xb = sdat + seq * SEQSTR;
    float* kb = xb + S * ROW;
    float* vb = kb + S * ROW;
    float* xrow = xb + tok * ROW;

    float qknQ[8], qknK[8];
#pragma unroll
    for (int e = 0; e < 8; e++) {
        qknQ[e] = sqkn[e] * 0.35355339059327373f;   // fold 1/sqrt(HD)
        qknK[e] = sqkn[8 + e];
    }

    float cs4[4], sn4[4];
    if (TEMPORAL) {
        const float th[4] = {1.f, 0.1f, 0.01f, 0.001f};
#pragma unroll
        for (int j = 0; j < 4; j++) __sincosf((float)tok * th[j], &sn4[j], &cs4[j]);
    }

    // ================= Phase B: h = rmsnorm(x); K,V,Q =======================
    u64 h2[16];
    {
        u64 x2[16];
        ld_row16(x2, xrow);
        float rs = rsqrtf(sumsq16(x2) * 0.03125f + 1e-6f);
        u64 rs2 = pack2(rs, rs);
        const ulonglong2* nw = (const ulonglong2*)snorm;
#pragma unroll
        for (int i = 0; i < 8; i++) {
            ulonglong2 n = nw[i];
            h2[2 * i] = mul2(mul2(x2[2 * i], rs2), n.x);
            h2[2 * i + 1] = mul2(mul2(x2[2 * i + 1], rs2), n.y);
        }
    }

    // ---- K heads ----
#pragma unroll 1
    for (int hh = 0; hh < 4; hh++) {
        float a[8];
#pragma unroll
        for (int e = 0; e < 8; e++) a[e] = dot32(swk + (hh * 8 + e) * 32, h2);
        float ms = 0;
#pragma unroll
        for (int e = 0; e < 8; e++) ms = fmaf(a[e], a[e], ms);
        float sc = rsqrtf(ms * 0.125f + 1e-6f);
#pragma unroll
        for (int e = 0; e < 8; e++) a[e] *= sc * qknK[e];
        if (TEMPORAL) {
#pragma unroll
            for (int e = 0; e < 4; e++) {
                float aa = a[e], bb = a[e + 4];
                a[e] = aa * cs4[e] - bb * sn4[e];
                a[e + 4] = fmaf(aa, sn4[e], bb * cs4[e]);
            }
        }
        if (valid) {
            float* dst = kb + tok * ROW + hh * 8;
            *(float4*)dst = make_float4(a[0], a[1], a[2], a[3]);
            *(float4*)(dst + 4) = make_float4(a[4], a[5], a[6], a[7]);
        }
    }

    // ---- V heads ----
#pragma unroll 1
    for (int hh = 0; hh < 4; hh++) {
        float a[8];
#pragma unroll
        for (int e = 0; e < 8; e++) a[e] = dot32(swv + (hh * 8 + e) * 32, h2);
        if (valid) {
            float* dst = vb + tok * ROW + hh * 8;
            *(float4*)dst = make_float4(a[0], a[1], a[2], a[3]);
            *(float4*)(dst + 4) = make_float4(a[4], a[5], a[6], a[7]);
        }
    }

    // ---- Q heads ----
    u64 q2[16];
#pragma unroll
    for (int hh = 0; hh < 4; hh++) {
        float a[8];
#pragma unroll
        for (int e = 0; e < 8; e++) a[e] = dot32(swq + (hh * 8 + e) * 32, h2);
        float ms = 0;
#pragma unroll
        for (int e = 0; e < 8; e++) ms = fmaf(a[e], a[e], ms);
        float sc = rsqrtf(ms * 0.125f + 1e-6f);
#pragma unroll
        for (int e = 0; e < 8; e++) a[e] *= sc * qknQ[e];
        if (TEMPORAL) {
#pragma unroll
            for (int e = 0; e < 4; e++) {
                float aa = a[e], bb = a[e + 4];
                a[e] = aa * cs4[e] - bb * sn4[e];
                a[e + 4] = fmaf(aa, sn4[e], bb * cs4[e]);
            }
        }
#pragma unroll
        for (int j = 0; j < 4; j++) q2[4 * hh + j] = pack2(a[2 * j], a[2 * j + 1]);
    }
    __syncthreads();

    // ================= Phase C: streaming attention ========================
    u64 o2[16];
#pragma unroll
    for (int i = 0; i < 16; i++) o2[i] = 0ULL;
    float l[4] = {0.f, 0.f, 0.f, 0.f};

#pragma unroll 1
    for (int j = 0; j < S; j++) {
        u64 k2[16], v2[16];
        ld_row16(k2, kb + j * ROW);
        ld_row16(v2, vb + j * ROW);
        float p[4];
#pragma unroll
        for (int hh = 0; hh < 4; hh++) {
            u64 c0 = fma2(q2[4 * hh + 1], k2[4 * hh + 1], mul2(q2[4 * hh], k2[4 * hh]));
            u64 c1 = fma2(q2[4 * hh + 3], k2[4 * hh + 3], mul2(q2[4 * hh + 2], k2[4 * hh + 2]));
            float s = hsum2(add2(c0, c1));
            p[hh] = __expf(s);
            l[hh] += p[hh];
        }
#pragma unroll
        for (int hh = 0; hh < 4; hh++) {
            u64 pp = pack2(p[hh], p[hh]);
#pragma unroll
            for (int i = 0; i < 4; i++)
                o2[4 * hh + i] = fma2(pp, v2[4 * hh + i], o2[4 * hh + i]);
        }
    }
#pragma unroll
    for (int hh = 0; hh < 4; hh++) {
        float li = __fdividef(1.f, l[hh]);
        u64 li2 = pack2(li, li);
#pragma unroll
        for (int i = 0; i < 4; i++) o2[4 * hh + i] = mul2(o2[4 * hh + i], li2);
    }

    // ---- Wo + rmsnorm residual ----
    float ow[32];
    float sumsq = 0.f;
#pragma unroll
    for (int d = 0; d < 32; d++) {
        ow[d] = dot32(swo + d * 32, o2);
        sumsq = fmaf(ow[d], ow[d], sumsq);
    }
    float rs1 = rsqrtf(sumsq * 0.03125f + 1e-6f);
    u64 rs12 = pack2(rs1, rs1);

    u64 xn2[16];
    {
        u64 x2[16];
        ld_row16(x2, xrow);          // LDS re-read (cheap)
        const ulonglong2* nw = (const ulonglong2*)(snorm + 32);
#pragma unroll
        for (int i = 0; i < 8; i++) {
            ulonglong2 n = nw[i];
            u64 w0 = pack2(ow[4 * i], ow[4 * i + 1]);
            u64 w1 = pack2(ow[4 * i + 2], ow[4 * i + 3]);
            xn2[2 * i] = fma2(mul2(w0, rs12), n.x, x2[2 * i]);
            xn2[2 * i + 1] = fma2(mul2(w1, rs12), n.y, x2[2 * i + 1]);
        }
    }

    // ---- h2v = rmsnorm(xn) ----
    u64 h2v[16];
    {
        float rs = rsqrtf(sumsq16(xn2) * 0.03125f + 1e-6f);
        u64 rs2 = pack2(rs, rs);
        const ulonglong2* nw = (const ulonglong2*)(snorm + 64);
#pragma unroll
        for (int i = 0; i < 8; i++) {
            ulonglong2 n = nw[i];
            h2v[2 * i] = mul2(mul2(xn2[2 * i], rs2), n.x);
            h2v[2 * i + 1] = mul2(mul2(xn2[2 * i + 1], rs2), n.y);
        }
    }

    // ---- FFN ----
    u64 ov2[16];
#pragma unroll
    for (int i = 0; i < 16; i++) ov2[i] = 0ULL;

#pragma unroll 1
    for (int fg = 0; fg < 16; fg++) {
#pragma unroll
        for (int e = 0; e < 4; e++) {
            int f = fg * 4 + e;
            float g = dot32(swg + f * 32, h2v);
            float u = dot32(swu + f * 32, h2v);
            float fv = __fdividef(g, 1.f + __expf(-g)) * u;
            u64 f2 = pack2(fv, fv);
            const ulonglong2* wr = (const ulonglong2*)(swout + f * 32);
#pragma unroll
            for (int i = 0; i < 8; i++) {
                ulonglong2 t = wr[i];
                ov2[2 * i] = fma2(f2, t.x, ov2[2 * i]);
                ov2[2 * i + 1] = fma2(f2, t.y, ov2[2 * i + 1]);
            }
        }
    }

    // ---- out = xn + rmsnorm(ov): write to own x row (output staging) ----
    {
        float rs3 = rsqrtf(sumsq16(ov2) * 0.03125f + 1e-6f);
        u64 rs32 = pack2(rs3, rs3);
        const ulonglong2* nw = (const ulonglong2*)(snorm + 96);
        if (valid) {
            ulonglong2* xo = (ulonglong2*)xrow;
#pragma unroll
            for (int i = 0; i < 8; i++) {
                ulonglong2 n = nw[i];
                ulonglong2 r;
                r.x = fma2(mul2(ov2[2 * i], rs32), n.x, xn2[2 * i]);
                r.y = fma2(mul2(ov2[2 * i + 1], rs32), n.y, xn2[2 * i + 1]);
                xo[i] = r;
            }
        }
    }
    __syncthreads();

    // ---- coalesced store: smem x-areas -> gmem ----
    for (int i = tid; i < nvalid * 8; i += BLK) {
        int token = i >> 3, part = i & 7;
        int sq = token / S, t = token - sq * S;
        float* dst;
        if (TEMPORAL) {
            int gs = gseq0 + sq;
            int b = gs / 67, sl = gs - b * 67;
            dst = g_tokens + ((long)(b * 128 + t) * 67 + sl) * 32 + 4 * part;
        } else {
            dst = g_tokens + (long)gseq0 * (67 * 32) + (long)i * 4;
        }
        *(float4*)dst = *(const float4*)(sdat + sq * SEQSTR + t * ROW + 4 * part);
    }
}

// ---------------------------------------------------------------------------
// Final: rmsnorm + extract 3 CLS tokens of last timestep.
// ---------------------------------------------------------------------------
__global__ void final_kernel(const float* __restrict__ fnorm, float* __restrict__ out) {
    int b = blockIdx.x / 3, k = blockIdx.x % 3, lane = threadIdx.x;
    float x = g_tokens[(((long)b * 128 + 127) * 67 + 64 + k) * 32 + lane];
    float ms = warp_sum(x * x) * (1.f / 32.f);
    out[(k * 16 + b) * 32 + lane] = x * rsqrtf(ms + 1e-6f) * fnorm[lane];
}

// ---------------------------------------------------------------------------
// Launch
// ---------------------------------------------------------------------------
extern "C" void kernel_launch(void* const* d_in, const int* in_sizes, int n_in,
                              void* d_out, int out_size) {
    const float* obs    = (const float*)d_in[0];
    const float* Wval   = (const float*)d_in[1];
    const float* bval   = (const float*)d_in[2];
    const float* innorm = (const float*)d_in[3];
    const float* dimemb = (const float*)d_in[4];
    const float* cls    = (const float*)d_in[5];
    const float* fnorm  = (const float*)d_in[6];
    const float* sWq   = (const float*)d_in[7];
    const float* sWk   = (const float*)d_in[8];
    const float* sWv   = (const float*)d_in[9];
    const float* sWo   = (const float*)d_in[10];
    const float* sWg   = (const float*)d_in[11];
    const float* sWu   = (const float*)d_in[12];
    const float* sWout = (const float*)d_in[13];
    const float* sN4   = (const float*)d_in[14];
    const float* sQKN  = (const float*)d_in[15];
    const float* tWq   = (const float*)d_in[16];
    const float* tWk   = (const float*)d_in[17];
    const float* tWv   = (const float*)d_in[18];
    const float* tWo   = (const float*)d_in[19];
    const float* tWg   = (const float*)d_in[20];
    const float* tWu   = (const float*)d_in[21];
    const float* tWout = (const float*)d_in[22];
    const float* tN4   = (const float*)d_in[23];
    const float* tQKN  = (const float*)d_in[24];

    // smem bytes: (NSEQ*3*S*36 + 10240 + 144) * 4
    const int SZ_S = (2 * 3 * 67 * 36 + 10240 + 144) * 4;    // 99424
    const int SZ_T = (2 * 3 * 128 * 36 + 10240 + 144) * 4;   // 152128

    cudaFuncSetAttribute(attn_tpl<67, 2, false>, cudaFuncAttributeMaxDynamicSharedMemorySize, SZ_S);
    cudaFuncSetAttribute(attn_tpl<128, 2, true>, cudaFuncAttributeMaxDynamicSharedMemorySize, SZ_T);

    embed_kernel<<<2048, 256>>>(obs, Wval, bval, innorm, dimemb, cls);

    const int GRID_S = 2048 / 2;   // 1024
    const int GRID_T = 1072 / 2;   // 536

    for (int layer = 0; layer < 3; layer++) {
        attn_tpl<67, 2, false><<<GRID_S, 160, SZ_S>>>(
            sWq + layer * 1024, sWk + layer * 1024, sWv + layer * 1024, sWo + layer * 1024,
            sWg + layer * 2048, sWu + layer * 2048, sWout + layer * 2048,
            sN4 + layer * 128, sQKN + layer * 16, 2048);
        if (layer < 2) {
            attn_tpl<128, 2, true><<<GRID_T, 256, SZ_T>>>(
                tWq + layer * 1024, tWk + layer * 1024, tWv + layer * 1024, tWo + layer * 1024,
                tWg + layer * 2048, tWu + layer * 2048, tWout + layer * 2048,
                tN4 + layer * 128, tQKN + layer * 16, 1072);
        }
    }

    final_kernel<<<48, 32>>>(fnorm, (float*)d_out);
}

// round 6
// speedup vs baseline: 1.1830x; 1.1830x over previous
#include <cuda_runtime.h>
#include <math.h>

#define FULL 0xffffffffu
typedef unsigned long long u64;

// Scratch token buffer: (B=16, T=128, slots=67, EMBED=32) fp32
__device__ float g_tokens[16 * 128 * 67 * 32];

__device__ __forceinline__ float warp_sum(float v) {
    v += __shfl_xor_sync(FULL, v, 16);
    v += __shfl_xor_sync(FULL, v, 8);
    v += __shfl_xor_sync(FULL, v, 4);
    v += __shfl_xor_sync(FULL, v, 2);
    v += __shfl_xor_sync(FULL, v, 1);
    return v;
}

// ---- packed f32x2 helpers ----
__device__ __forceinline__ u64 fma2(u64 a, u64 b, u64 c) {
    u64 d; asm("fma.rn.f32x2 %0, %1, %2, %3;" : "=l"(d) : "l"(a), "l"(b), "l"(c)); return d;
}
__device__ __forceinline__ u64 mul2(u64 a, u64 b) {
    u64 d; asm("mul.rn.f32x2 %0, %1, %2;" : "=l"(d) : "l"(a), "l"(b)); return d;
}
__device__ __forceinline__ u64 add2(u64 a, u64 b) {
    u64 d; asm("add.rn.f32x2 %0, %1, %2;" : "=l"(d) : "l"(a), "l"(b)); return d;
}
__device__ __forceinline__ u64 pack2(float lo, float hi) {
    u64 d; asm("mov.b64 %0, {%1, %2};" : "=l"(d) : "f"(lo), "f"(hi)); return d;
}
__device__ __forceinline__ float hsum2(u64 v) {
    float lo, hi; asm("mov.b64 {%0, %1}, %2;" : "=f"(lo), "=f"(hi) : "l"(v)); return lo + hi;
}

__device__ __forceinline__ void ld_row16(u64* r, const float* p) {
    const ulonglong2* q = (const ulonglong2*)p;
#pragma unroll
    for (int i = 0; i < 8; i++) { ulonglong2 t = q[i]; r[2 * i] = t.x; r[2 * i + 1] = t.y; }
}

// one weight row read, TWO dots (token pair) -> 2x weight-LDS amortization
__device__ __forceinline__ float2 dot32x2(const float* wrow, const u64* a, const u64* b) {
    const ulonglong2* w = (const ulonglong2*)wrow;
    ulonglong2 t0 = w[0], t1 = w[1];
    u64 a0 = mul2(a[0], t0.x), b0 = mul2(b[0], t0.x);
    a0 = fma2(a[1], t0.y, a0); b0 = fma2(b[1], t0.y, b0);
    u64 a1 = mul2(a[2], t1.x), b1 = mul2(b[2], t1.x);
    a1 = fma2(a[3], t1.y, a1); b1 = fma2(b[3], t1.y, b1);
#pragma unroll
    for (int i = 2; i < 8; i += 2) {
        ulonglong2 u0 = w[i], u1 = w[i + 1];
        a0 = fma2(a[2 * i], u0.x, a0);     b0 = fma2(b[2 * i], u0.x, b0);
        a0 = fma2(a[2 * i + 1], u0.y, a0); b0 = fma2(b[2 * i + 1], u0.y, b0);
        a1 = fma2(a[2 * i + 2], u1.x, a1); b1 = fma2(b[2 * i + 2], u1.x, b1);
        a1 = fma2(a[2 * i + 3], u1.y, a1); b1 = fma2(b[2 * i + 3], u1.y, b1);
    }
    return make_float2(hsum2(add2(a0, a1)), hsum2(add2(b0, b1)));
}

__device__ __forceinline__ float sumsq16(const u64* v) {
    u64 a0 = mul2(v[0], v[0]);
    u64 a1 = mul2(v[1], v[1]);
#pragma unroll
    for (int i = 2; i < 16; i += 2) {
        a0 = fma2(v[i], v[i], a0);
        a1 = fma2(v[i + 1], v[i + 1], a1);
    }
    return hsum2(add2(a0, a1));
}

// ---------------------------------------------------------------------------
// Kernel 0: tokenize + input rmsnorm. grid = B*T (2048), block = 256.
// ---------------------------------------------------------------------------
__global__ void embed_kernel(const float* __restrict__ obs,
                             const float* __restrict__ Wval,
                             const float* __restrict__ bval,
                             const float* __restrict__ innorm,
                             const float* __restrict__ dimemb,
                             const float* __restrict__ cls) {
    int bt = blockIdx.x;
    int tid = threadIdx.x;
    int wid = tid >> 5, lane = tid & 31;
    for (int s = wid; s < 67; s += 8) {
        float val;
        if (s < 64)
            val = fmaf(obs[bt * 64 + s], Wval[lane], bval[lane]) + dimemb[s * 32 + lane];
        else
            val = cls[(s - 64) * 32 + lane];
        float ms = warp_sum(val * val) * (1.f / 32.f);
        g_tokens[(bt * 67 + s) * 32 + lane] = val * rsqrtf(ms + 1e-6f) * innorm[lane];
    }
}

// ---------------------------------------------------------------------------
// Fused attention block: TWO tokens per lane (tok, tok+ceil(S/2), same seq).
// Every weight/K/V smem broadcast serves 64 tokens per warp-pass.
// K-area doubles as xn storage after attention (guarded by a syncthreads).
// ---------------------------------------------------------------------------
template <int S, int NSEQ, bool TEMPORAL>
__global__ void __launch_bounds__(32 * ((((S + 1) / 2) * NSEQ + 31) / 32))
attn_tpl(const float* __restrict__ Wq, const float* __restrict__ Wk,
         const float* __restrict__ Wv, const float* __restrict__ Wo,
         const float* __restrict__ Wg, const float* __restrict__ Wu,
         const float* __restrict__ Wout, const float* __restrict__ norm4,
         const float* __restrict__ qkn, int nseq_total) {
    constexpr int HS = (S + 1) / 2;
    constexpr int BLK = 32 * ((HS * NSEQ + 31) / 32);
    constexpr int ROW = 36;
    constexpr int SEQSTR = 2 * S * ROW;      // k,v per sequence
    constexpr int DATSZ = NSEQ * SEQSTR;

    extern __shared__ float sm[];
    float* skv   = sm;                 // DATSZ
    float* swq   = skv + DATSZ;        // 1024
    float* swk   = swq + 1024;
    float* swv   = swk + 1024;
    float* swo   = swv + 1024;
    float* swg   = swo + 1024;         // 2048
    float* swu   = swg + 2048;         // 2048
    float* swout = swu + 2048;         // 2048 transposed [f][d]
    float* snorm = swout + 2048;       // 128
    float* sqkn  = snorm + 128;        // 16

    const int tid = threadIdx.x;
    int gseq0 = blockIdx.x * NSEQ;

    // ---- stage weights ----
    for (int i = tid; i < 256; i += BLK) {
        ((float4*)swq)[i] = ((const float4*)Wq)[i];
        ((float4*)swk)[i] = ((const float4*)Wk)[i];
        ((float4*)swv)[i] = ((const float4*)Wv)[i];
        ((float4*)swo)[i] = ((const float4*)Wo)[i];
    }
    for (int i = tid; i < 512; i += BLK) {
        ((float4*)swg)[i] = ((const float4*)Wg)[i];
        ((float4*)swu)[i] = ((const float4*)Wu)[i];
    }
    for (int i = tid; i < 2048; i += BLK) {   // transpose Wout -> [f][d]
        int f = i >> 5, d = i & 31;
        swout[i] = Wout[d * 64 + f];
    }
    if (tid < 128) snorm[tid] = norm4[tid];
    if (tid < 16) sqkn[tid] = qkn[tid];

    // ---- token-pair assignment ----
    int seq = tid / HS;
    int l = tid - seq * HS;
    bool seqok = (seq < NSEQ) && (gseq0 + seq < nseq_total);
    int seqc = seqok ? seq : 0;
    bool vA = seqok;                 // tokA = l < HS <= S always
    bool vB = seqok && (l + HS < S);
    int tokA = l;
    int tokB = vB ? (l + HS) : (S - 1);

    float* kb = skv + seqc * SEQSTR;
    float* vb = kb + S * ROW;

    float *gxA, *gxB;
    {
        int gs = gseq0 + seqc;
        if (TEMPORAL) {
            int b = gs / 67, sl = gs - b * 67;
            gxA = g_tokens + ((long)(b * 128 + tokA) * 67 + sl) * 32;
            gxB = g_tokens + ((long)(b * 128 + tokB) * 67 + sl) * 32;
        } else {
            gxA = g_tokens + ((long)gs * 67 + tokA) * 32;
            gxB = g_tokens + ((long)gs * 67 + tokB) * 32;
        }
    }

    __syncthreads();

    u64 qA[16], qB[16];

    // ================= Phase B: norm + QKV (+qk-norm, rope) ================
    if (vA) {
        float qknQ[8], qknK[8];
#pragma unroll
        for (int e = 0; e < 8; e++) {
            qknQ[e] = sqkn[e] * 0.35355339059327373f;   // fold 1/sqrt(HD)
            qknK[e] = sqkn[8 + e];
        }
        float csA[4], snA[4], csB[4], snB[4];
        if (TEMPORAL) {
            const float th[4] = {1.f, 0.1f, 0.01f, 0.001f};
#pragma unroll
            for (int j = 0; j < 4; j++) {
                __sincosf((float)tokA * th[j], &snA[j], &csA[j]);
                __sincosf((float)tokB * th[j], &snB[j], &csB[j]);
            }
        }

        u64 hA[16], hB[16];
        {
            u64 x2[16];
            ld_row16(x2, gxA);
            float rs = rsqrtf(sumsq16(x2) * 0.03125f + 1e-6f);
            u64 rs2 = pack2(rs, rs);
            const ulonglong2* nw = (const ulonglong2*)snorm;
#pragma unroll
            for (int i = 0; i < 8; i++) {
                ulonglong2 n = nw[i];
                hA[2 * i] = mul2(mul2(x2[2 * i], rs2), n.x);
                hA[2 * i + 1] = mul2(mul2(x2[2 * i + 1], rs2), n.y);
            }
            ld_row16(x2, gxB);
            rs = rsqrtf(sumsq16(x2) * 0.03125f + 1e-6f);
            rs2 = pack2(rs, rs);
#pragma unroll
            for (int i = 0; i < 8; i++) {
                ulonglong2 n = nw[i];
                hB[2 * i] = mul2(mul2(x2[2 * i], rs2), n.x);
                hB[2 * i + 1] = mul2(mul2(x2[2 * i + 1], rs2), n.y);
            }
        }

        // ---- K heads ----
#pragma unroll 1
        for (int hh = 0; hh < 4; hh++) {
            float aA[8], aB[8];
#pragma unroll
            for (int e = 0; e < 8; e++) {
                float2 d = dot32x2(swk + (hh * 8 + e) * 32, hA, hB);
                aA[e] = d.x; aB[e] = d.y;
            }
            float msA = 0, msB = 0;
#pragma unroll
            for (int e = 0; e < 8; e++) { msA = fmaf(aA[e], aA[e], msA); msB = fmaf(aB[e], aB[e], msB); }
            float scA = rsqrtf(msA * 0.125f + 1e-6f);
            float scB = rsqrtf(msB * 0.125f + 1e-6f);
#pragma unroll
            for (int e = 0; e < 8; e++) { aA[e] *= scA * qknK[e]; aB[e] *= scB * qknK[e]; }
            if (TEMPORAL) {
#pragma unroll
                for (int e = 0; e < 4; e++) {
                    float t0 = aA[e], t1 = aA[e + 4];
                    aA[e] = t0 * csA[e] - t1 * snA[e];
                    aA[e + 4] = fmaf(t0, snA[e], t1 * csA[e]);
                    t0 = aB[e]; t1 = aB[e + 4];
                    aB[e] = t0 * csB[e] - t1 * snB[e];
                    aB[e + 4] = fmaf(t0, snB[e], t1 * csB[e]);
                }
            }
            float* dA = kb + tokA * ROW + hh * 8;
            *(float4*)dA = make_float4(aA[0], aA[1], aA[2], aA[3]);
            *(float4*)(dA + 4) = make_float4(aA[4], aA[5], aA[6], aA[7]);
            if (vB) {
                float* dB = kb + tokB * ROW + hh * 8;
                *(float4*)dB = make_float4(aB[0], aB[1], aB[2], aB[3]);
                *(float4*)(dB + 4) = make_float4(aB[4], aB[5], aB[6], aB[7]);
            }
        }

        // ---- V heads ----
#pragma unroll 1
        for (int hh = 0; hh < 4; hh++) {
            float aA[8], aB[8];
#pragma unroll
            for (int e = 0; e < 8; e++) {
                float2 d = dot32x2(swv + (hh * 8 + e) * 32, hA, hB);
                aA[e] = d.x; aB[e] = d.y;
            }
            float* dA = vb + tokA * ROW + hh * 8;
            *(float4*)dA = make_float4(aA[0], aA[1], aA[2], aA[3]);
            *(float4*)(dA + 4) = make_float4(aA[4], aA[5], aA[6], aA[7]);
            if (vB) {
                float* dB = vb + tokB * ROW + hh * 8;
                *(float4*)dB = make_float4(aB[0], aB[1], aB[2], aB[3]);
                *(float4*)(dB + 4) = make_float4(aB[4], aB[5], aB[6], aB[7]);
            }
        }

        // ---- Q heads ----
#pragma unroll
        for (int hh = 0; hh < 4; hh++) {
            float aA[8], aB[8];
#pragma unroll
            for (int e = 0; e < 8; e++) {
                float2 d = dot32x2(swq + (hh * 8 + e) * 32, hA, hB);
                aA[e] = d.x; aB[e] = d.y;
            }
            float msA = 0, msB = 0;
#pragma unroll
            for (int e = 0; e < 8; e++) { msA = fmaf(aA[e], aA[e], msA); msB = fmaf(aB[e], aB[e], msB); }
            float scA = rsqrtf(msA * 0.125f + 1e-6f);
            float scB = rsqrtf(msB * 0.125f + 1e-6f);
#pragma unroll
            for (int e = 0; e < 8; e++) { aA[e] *= scA * qknQ[e]; aB[e] *= scB * qknQ[e]; }
            if (TEMPORAL) {
#pragma unroll
                for (int e = 0; e < 4; e++) {
                    float t0 = aA[e], t1 = aA[e + 4];
                    aA[e] = t0 * csA[e] - t1 * snA[e];
                    aA[e + 4] = fmaf(t0, snA[e], t1 * csA[e]);
                    t0 = aB[e]; t1 = aB[e + 4];
                    aB[e] = t0 * csB[e] - t1 * snB[e];
                    aB[e + 4] = fmaf(t0, snB[e], t1 * csB[e]);
                }
            }
#pragma unroll
            for (int j = 0; j < 4; j++) {
                qA[4 * hh + j] = pack2(aA[2 * j], aA[2 * j + 1]);
                qB[4 * hh + j] = pack2(aB[2 * j], aB[2 * j + 1]);
            }
        }
    }
    __syncthreads();

    // ================= Phase C: streaming attention ========================
    u64 oA[16], oB[16];
    float lA[4], lB[4];
    if (vA) {
#pragma unroll
        for (int i = 0; i < 16; i++) { oA[i] = 0ULL; oB[i] = 0ULL; }
#pragma unroll
        for (int h = 0; h < 4; h++) { lA[h] = 0.f; lB[h] = 0.f; }

#pragma unroll 1
        for (int j = 0; j < S; j++) {
            u64 r2[16];
            ld_row16(r2, kb + j * ROW);
            float pA[4], pB[4];
#pragma unroll
            for (int hh = 0; hh < 4; hh++) {
                u64 cA = fma2(qA[4 * hh + 1], r2[4 * hh + 1], mul2(qA[4 * hh], r2[4 * hh]));
                u64 dA = fma2(qA[4 * hh + 3], r2[4 * hh + 3], mul2(qA[4 * hh + 2], r2[4 * hh + 2]));
                pA[hh] = __expf(hsum2(add2(cA, dA)));
                lA[hh] += pA[hh];
                u64 cB = fma2(qB[4 * hh + 1], r2[4 * hh + 1], mul2(qB[4 * hh], r2[4 * hh]));
                u64 dB = fma2(qB[4 * hh + 3], r2[4 * hh + 3], mul2(qB[4 * hh + 2], r2[4 * hh + 2]));
                pB[hh] = __expf(hsum2(add2(cB, dB)));
                lB[hh] += pB[hh];
            }
            ld_row16(r2, vb + j * ROW);
#pragma unroll
            for (int hh = 0; hh < 4; hh++) {
                u64 ppA = pack2(pA[hh], pA[hh]);
                u64 ppB = pack2(pB[hh], pB[hh]);
#pragma unroll
                for (int i = 0; i < 4; i++) {
                    oA[4 * hh + i] = fma2(ppA, r2[4 * hh + i], oA[4 * hh + i]);
                    oB[4 * hh + i] = fma2(ppB, r2[4 * hh + i], oB[4 * hh + i]);
                }
            }
        }
#pragma unroll
        for (int hh = 0; hh < 4; hh++) {
            u64 liA = pack2(__fdividef(1.f, lA[hh]), __fdividef(1.f, lA[hh]));
            u64 liB = pack2(__fdividef(1.f, lB[hh]), __fdividef(1.f, lB[hh]));
#pragma unroll
            for (int i = 0; i < 4; i++) {
                oA[4 * hh + i] = mul2(oA[4 * hh + i], liA);
                oB[4 * hh + i] = mul2(oB[4 * hh + i], liB);
            }
        }
    }
    __syncthreads();   // all warps done reading k/v -> k-area reusable for xn

    // ================= Phase D: Wo + residual + FFN + residual =============
    if (vA) {
        float owA[32], owB[32];
        float ssA = 0.f, ssB = 0.f;
#pragma unroll
        for (int d = 0; d < 32; d++) {
            float2 r = dot32x2(swo + d * 32, oA, oB);
            owA[d] = r.x; owB[d] = r.y;
            ssA = fmaf(r.x, r.x, ssA);
            ssB = fmaf(r.y, r.y, ssB);
        }
        u64 rsA = pack2(rsqrtf(ssA * 0.03125f + 1e-6f), rsqrtf(ssA * 0.03125f + 1e-6f));
        u64 rsB = pack2(rsqrtf(ssB * 0.03125f + 1e-6f), rsqrtf(ssB * 0.03125f + 1e-6f));

        u64 h2A[16], h2B[16];
        {
            // xnA -> k-area row tokA; keep h2 (rmsnorm of xn) in regs
            u64 x2[16], xn[16];
            const ulonglong2* nw1 = (const ulonglong2*)(snorm + 32);
            ld_row16(x2, gxA);
#pragma unroll
            for (int i = 0; i < 8; i++) {
                ulonglong2 n = nw1[i];
                xn[2 * i] = fma2(mul2(pack2(owA[4 * i], owA[4 * i + 1]), rsA), n.x, x2[2 * i]);
                xn[2 * i + 1] = fma2(mul2(pack2(owA[4 * i + 2], owA[4 * i + 3]), rsA), n.y, x2[2 * i + 1]);
            }
            {
                ulonglong2* xo = (ulonglong2*)(kb + tokA * ROW);
#pragma unroll
                for (int i = 0; i < 8; i++) { ulonglong2 t; t.x = xn[2 * i]; t.y = xn[2 * i + 1]; xo[i] = t; }
            }
            float rs = rsqrtf(sumsq16(xn) * 0.03125f + 1e-6f);
            u64 rs2 = pack2(rs, rs);
            const ulonglong2* nw2 = (const ulonglong2*)(snorm + 64);
#pragma unroll
            for (int i = 0; i < 8; i++) {
                ulonglong2 n = nw2[i];
                h2A[2 * i] = mul2(mul2(xn[2 * i], rs2), n.x);
                h2A[2 * i + 1] = mul2(mul2(xn[2 * i + 1], rs2), n.y);
            }
            // token B
            ld_row16(x2, gxB);
#pragma unroll
            for (int i = 0; i < 8; i++) {
                ulonglong2 n = nw1[i];
                xn[2 * i] = fma2(mul2(pack2(owB[4 * i], owB[4 * i + 1]), rsB), n.x, x2[2 * i]);
                xn[2 * i + 1] = fma2(mul2(pack2(owB[4 * i + 2], owB[4 * i + 3]), rsB), n.y, x2[2 * i + 1]);
            }
            if (vB) {
                ulonglong2* xo = (ulonglong2*)(kb + tokB * ROW);
#pragma unroll
                for (int i = 0; i < 8; i++) { ulonglong2 t; t.x = xn[2 * i]; t.y = xn[2 * i + 1]; xo[i] = t; }
            }
            rs = rsqrtf(sumsq16(xn) * 0.03125f + 1e-6f);
            rs2 = pack2(rs, rs);
#pragma unroll
            for (int i = 0; i < 8; i++) {
                ulonglong2 n = nw2[i];
                h2B[2 * i] = mul2(mul2(xn[2 * i], rs2), n.x);
                h2B[2 * i + 1] = mul2(mul2(xn[2 * i + 1], rs2), n.y);
            }
        }

        // ---- FFN ----
        u64 ovA[16], ovB[16];
#pragma unroll
        for (int i = 0; i < 16; i++) { ovA[i] = 0ULL; ovB[i] = 0ULL; }

#pragma unroll 1
        for (int fg = 0; fg < 16; fg++) {
#pragma unroll
            for (int e = 0; e < 4; e++) {
                int f = fg * 4 + e;
                float2 g2 = dot32x2(swg + f * 32, h2A, h2B);
                float2 u2 = dot32x2(swu + f * 32, h2A, h2B);
                float fvA = __fdividef(g2.x, 1.f + __expf(-g2.x)) * u2.x;
                float fvB = __fdividef(g2.y, 1.f + __expf(-g2.y)) * u2.y;
                u64 fA = pack2(fvA, fvA), fB = pack2(fvB, fvB);
                const ulonglong2* wr = (const ulonglong2*)(swout + f * 32);
#pragma unroll
                for (int i = 0; i < 8; i++) {
                    ulonglong2 t = wr[i];
                    ovA[2 * i] = fma2(fA, t.x, ovA[2 * i]);
                    ovA[2 * i + 1] = fma2(fA, t.y, ovA[2 * i + 1]);
                    ovB[2 * i] = fma2(fB, t.x, ovB[2 * i]);
                    ovB[2 * i + 1] = fma2(fB, t.y, ovB[2 * i + 1]);
                }
            }
        }

        // ---- out = xn + rmsnorm(ov), reload xn from k-area, store gmem ----
        {
            const ulonglong2* nw = (const ulonglong2*)(snorm + 96);
            float rs3 = rsqrtf(sumsq16(ovA) * 0.03125f + 1e-6f);
            u64 rs32 = pack2(rs3, rs3);
            u64 xn[16];
            ld_row16(xn, kb + tokA * ROW);
            ulonglong2* go = (ulonglong2*)gxA;
#pragma unroll
            for (int i = 0; i < 8; i++) {
                ulonglong2 n = nw[i];
                ulonglong2 r;
                r.x = fma2(mul2(ovA[2 * i], rs32), n.x, xn[2 * i]);
                r.y = fma2(mul2(ovA[2 * i + 1], rs32), n.y, xn[2 * i + 1]);
                go[i] = r;
            }
            if (vB) {
                rs3 = rsqrtf(sumsq16(ovB) * 0.03125f + 1e-6f);
                rs32 = pack2(rs3, rs3);
                ld_row16(xn, kb + tokB * ROW);
                go = (ulonglong2*)gxB;
#pragma unroll
                for (int i = 0; i < 8; i++) {
                    ulonglong2 n = nw[i];
                    ulonglong2 r;
                    r.x = fma2(mul2(ovB[2 * i], rs32), n.x, xn[2 * i]);
                    r.y = fma2(mul2(ovB[2 * i + 1], rs32), n.y, xn[2 * i + 1]);
                    go[i] = r;
                }
            }
        }
    }
}

// ---------------------------------------------------------------------------
// Final: rmsnorm + extract 3 CLS tokens of last timestep.
// ---------------------------------------------------------------------------
__global__ void final_kernel(const float* __restrict__ fnorm, float* __restrict__ out) {
    int b = blockIdx.x / 3, k = blockIdx.x % 3, lane = threadIdx.x;
    float x = g_tokens[(((long)b * 128 + 127) * 67 + 64 + k) * 32 + lane];
    float ms = warp_sum(x * x) * (1.f / 32.f);
    out[(k * 16 + b) * 32 + lane] = x * rsqrtf(ms + 1e-6f) * fnorm[lane];
}

// ---------------------------------------------------------------------------
// Launch
// ---------------------------------------------------------------------------
extern "C" void kernel_launch(void* const* d_in, const int* in_sizes, int n_in,
                              void* d_out, int out_size) {
    const float* obs    = (const float*)d_in[0];
    const float* Wval   = (const float*)d_in[1];
    const float* bval   = (const float*)d_in[2];
    const float* innorm = (const float*)d_in[3];
    const float* dimemb = (const float*)d_in[4];
    const float* cls    = (const float*)d_in[5];
    const float* fnorm  = (const float*)d_in[6];
    const float* sWq   = (const float*)d_in[7];
    const float* sWk   = (const float*)d_in[8];
    const float* sWv   = (const float*)d_in[9];
    const float* sWo   = (const float*)d_in[10];
    const float* sWg   = (const float*)d_in[11];
    const float* sWu   = (const float*)d_in[12];
    const float* sWout = (const float*)d_in[13];
    const float* sN4   = (const float*)d_in[14];
    const float* sQKN  = (const float*)d_in[15];
    const float* tWq   = (const float*)d_in[16];
    const float* tWk   = (const float*)d_in[17];
    const float* tWv   = (const float*)d_in[18];
    const float* tWo   = (const float*)d_in[19];
    const float* tWg   = (const float*)d_in[20];
    const float* tWu   = (const float*)d_in[21];
    const float* tWout = (const float*)d_in[22];
    const float* tN4   = (const float*)d_in[23];
    const float* tQKN  = (const float*)d_in[24];

    // smem floats: NSEQ*2*S*36 + 10240 + 144
    const int SZ_S = (3 * 2 * 67 * 36 + 10240 + 144) * 4;    // 99424
    const int SZ_T = (4 * 2 * 128 * 36 + 10240 + 144) * 4;   // 188992

    cudaFuncSetAttribute(attn_tpl<67, 3, false>, cudaFuncAttributeMaxDynamicSharedMemorySize, SZ_S);
    cudaFuncSetAttribute(attn_tpl<128, 4, true>, cudaFuncAttributeMaxDynamicSharedMemorySize, SZ_T);

    embed_kernel<<<2048, 256>>>(obs, Wval, bval, innorm, dimemb, cls);

    const int GRID_S = (2048 + 2) / 3;   // 683
    const int GRID_T = 1072 / 4;         // 268

    for (int layer = 0; layer < 3; layer++) {
        attn_tpl<67, 3, false><<<GRID_S, 128, SZ_S>>>(
            sWq + layer * 1024, sWk + layer * 1024, sWv + layer * 1024, sWo + layer * 1024,
            sWg + layer * 2048, sWu + layer * 2048, sWout + layer * 2048,
            sN4 + layer * 128, sQKN + layer * 16, 2048);
        if (layer < 2) {
            attn_tpl<128, 4, true><<<GRID_T, 256, SZ_T>>>(
                tWq + layer * 1024, tWk + layer * 1024, tWv + layer * 1024, tWo + layer * 1024,
                tWg + layer * 2048, tWu + layer * 2048, tWout + layer * 2048,
                tN4 + layer * 128, tQKN + layer * 16, 1072);
        }
    }

    final_kernel<<<48, 32>>>(fnorm, (float*)d_out);
}

// round 7
// speedup vs baseline: 1.1948x; 1.0100x over previous
#include <cuda_runtime.h>
#include <math.h>

#define FULL 0xffffffffu
typedef unsigned long long u64;

// Scratch token buffer: (B=16, T=128, slots=67, EMBED=32) fp32
__device__ float g_tokens[16 * 128 * 67 * 32];

__device__ __forceinline__ float warp_sum(float v) {
    v += __shfl_xor_sync(FULL, v, 16);
    v += __shfl_xor_sync(FULL, v, 8);
    v += __shfl_xor_sync(FULL, v, 4);
    v += __shfl_xor_sync(FULL, v, 2);
    v += __shfl_xor_sync(FULL, v, 1);
    return v;
}

// ---- packed f32x2 helpers ----
__device__ __forceinline__ u64 fma2(u64 a, u64 b, u64 c) {
    u64 d; asm("fma.rn.f32x2 %0, %1, %2, %3;" : "=l"(d) : "l"(a), "l"(b), "l"(c)); return d;
}
__device__ __forceinline__ u64 mul2(u64 a, u64 b) {
    u64 d; asm("mul.rn.f32x2 %0, %1, %2;" : "=l"(d) : "l"(a), "l"(b)); return d;
}
__device__ __forceinline__ u64 add2(u64 a, u64 b) {
    u64 d; asm("add.rn.f32x2 %0, %1, %2;" : "=l"(d) : "l"(a), "l"(b)); return d;
}
__device__ __forceinline__ u64 pack2(float lo, float hi) {
    u64 d; asm("mov.b64 %0, {%1, %2};" : "=l"(d) : "f"(lo), "f"(hi)); return d;
}
__device__ __forceinline__ float hsum2(u64 v) {
    float lo, hi; asm("mov.b64 {%0, %1}, %2;" : "=f"(lo), "=f"(hi) : "l"(v)); return lo + hi;
}
// base-2 exp, scores pre-scaled by log2(e)
__device__ __forceinline__ float ex2f(float x) {
    float y; asm("ex2.approx.f32 %0, %1;" : "=f"(y) : "f"(x)); return y;
}

__device__ __forceinline__ void ld_row16(u64* r, const float* p) {
    const ulonglong2* q = (const ulonglong2*)p;
#pragma unroll
    for (int i = 0; i < 8; i++) { ulonglong2 t = q[i]; r[2 * i] = t.x; r[2 * i + 1] = t.y; }
}

// one weight row read, TWO dots (token pair) -> 2x weight-LDS amortization
__device__ __forceinline__ float2 dot32x2(const float* wrow, const u64* a, const u64* b) {
    const ulonglong2* w = (const ulonglong2*)wrow;
    ulonglong2 t0 = w[0], t1 = w[1];
    u64 a0 = mul2(a[0], t0.x), b0 = mul2(b[0], t0.x);
    a0 = fma2(a[1], t0.y, a0); b0 = fma2(b[1], t0.y, b0);
    u64 a1 = mul2(a[2], t1.x), b1 = mul2(b[2], t1.x);
    a1 = fma2(a[3], t1.y, a1); b1 = fma2(b[3], t1.y, b1);
#pragma unroll
    for (int i = 2; i < 8; i += 2) {
        ulonglong2 u0 = w[i], u1 = w[i + 1];
        a0 = fma2(a[2 * i], u0.x, a0);     b0 = fma2(b[2 * i], u0.x, b0);
        a0 = fma2(a[2 * i + 1], u0.y, a0); b0 = fma2(b[2 * i + 1], u0.y, b0);
        a1 = fma2(a[2 * i + 2], u1.x, a1); b1 = fma2(b[2 * i + 2], u1.x, b1);
        a1 = fma2(a[2 * i + 3], u1.y, a1); b1 = fma2(b[2 * i + 3], u1.y, b1);
    }
    return make_float2(hsum2(add2(a0, a1)), hsum2(add2(b0, b1)));
}

__device__ __forceinline__ float sumsq16(const u64* v) {
    u64 a0 = mul2(v[0], v[0]);
    u64 a1 = mul2(v[1], v[1]);
#pragma unroll
    for (int i = 2; i < 16; i += 2) {
        a0 = fma2(v[i], v[i], a0);
        a1 = fma2(v[i + 1], v[i + 1], a1);
    }
    return hsum2(add2(a0, a1));
}

// ---------------------------------------------------------------------------
// Kernel 0: tokenize + input rmsnorm. grid = B*T (2048), block = 256.
// ---------------------------------------------------------------------------
__global__ void embed_kernel(const float* __restrict__ obs,
                             const float* __restrict__ Wval,
                             const float* __restrict__ bval,
                             const float* __restrict__ innorm,
                             const float* __restrict__ dimemb,
                             const float* __restrict__ cls) {
    int bt = blockIdx.x;
    int tid = threadIdx.x;
    int wid = tid >> 5, lane = tid & 31;
    for (int s = wid; s < 67; s += 8) {
        float val;
        if (s < 64)
            val = fmaf(obs[bt * 64 + s], Wval[lane], bval[lane]) + dimemb[s * 32 + lane];
        else
            val = cls[(s - 64) * 32 + lane];
        float ms = warp_sum(val * val) * (1.f / 32.f);
        g_tokens[(bt * 67 + s) * 32 + lane] = val * rsqrtf(ms + 1e-6f) * innorm[lane];
    }
}

// ---------------------------------------------------------------------------
// Fused attention block: TWO tokens per lane (tok, tok+ceil(S/2), same seq).
// Every weight/K/V smem broadcast serves 64 tokens per warp-pass.
// K-area doubles as xn storage after attention (guarded by a syncthreads).
// Softmax in base-2 domain (log2e folded into Q scale) -> raw ex2.approx.
// ---------------------------------------------------------------------------
template <int S, int NSEQ, bool TEMPORAL>
__global__ void __launch_bounds__(32 * ((((S + 1) / 2) * NSEQ + 31) / 32))
attn_tpl(const float* __restrict__ Wq, const float* __restrict__ Wk,
         const float* __restrict__ Wv, const float* __restrict__ Wo,
         const float* __restrict__ Wg, const float* __restrict__ Wu,
         const float* __restrict__ Wout, const float* __restrict__ norm4,
         const float* __restrict__ qkn, int nseq_total) {
    constexpr int HS = (S + 1) / 2;
    constexpr int BLK = 32 * ((HS * NSEQ + 31) / 32);
    constexpr int ROW = 36;
    constexpr int SEQSTR = 2 * S * ROW;      // k,v per sequence
    constexpr int DATSZ = NSEQ * SEQSTR;

    extern __shared__ float sm[];
    float* skv   = sm;                 // DATSZ
    float* swq   = skv + DATSZ;        // 1024
    float* swk   = swq + 1024;
    float* swv   = swk + 1024;
    float* swo   = swv + 1024;
    float* swg   = swo + 1024;         // 2048
    float* swu   = swg + 2048;         // 2048
    float* swout = swu + 2048;         // 2048 transposed [f][d]
    float* snorm = swout + 2048;       // 128
    float* sqkn  = snorm + 128;        // 16

    const int tid = threadIdx.x;
    int gseq0 = blockIdx.x * NSEQ;

    // ---- stage weights ----
    for (int i = tid; i < 256; i += BLK) {
        ((float4*)swq)[i] = ((const float4*)Wq)[i];
        ((float4*)swk)[i] = ((const float4*)Wk)[i];
        ((float4*)swv)[i] = ((const float4*)Wv)[i];
        ((float4*)swo)[i] = ((const float4*)Wo)[i];
    }
    for (int i = tid; i < 512; i += BLK) {
        ((float4*)swg)[i] = ((const float4*)Wg)[i];
        ((float4*)swu)[i] = ((const float4*)Wu)[i];
    }
    for (int i = tid; i < 2048; i += BLK) {   // transpose Wout -> [f][d]
        int f = i >> 5, d = i & 31;
        swout[i] = Wout[d * 64 + f];
    }
    if (tid < 128) snorm[tid] = norm4[tid];
    if (tid < 16) sqkn[tid] = qkn[tid];

    // ---- token-pair assignment ----
    int seq = tid / HS;
    int l = tid - seq * HS;
    bool seqok = (seq < NSEQ) && (gseq0 + seq < nseq_total);
    int seqc = seqok ? seq : 0;
    bool vA = seqok;                 // tokA = l < HS <= S always
    bool vB = seqok && (l + HS < S);
    int tokA = l;
    int tokB = vB ? (l + HS) : (S - 1);

    float* kb = skv + seqc * SEQSTR;
    float* vb = kb + S * ROW;

    float *gxA, *gxB;
    {
        int gs = gseq0 + seqc;
        if (TEMPORAL) {
            int b = gs / 67, sl = gs - b * 67;
            gxA = g_tokens + ((long)(b * 128 + tokA) * 67 + sl) * 32;
            gxB = g_tokens + ((long)(b * 128 + tokB) * 67 + sl) * 32;
        } else {
            gxA = g_tokens + ((long)gs * 67 + tokA) * 32;
            gxB = g_tokens + ((long)gs * 67 + tokB) * 32;
        }
    }

    __syncthreads();

    u64 qA[16], qB[16];

    // ================= Phase B: norm + QKV (+qk-norm, rope) ================
    if (vA) {
        float qknQ[8], qknK[8];
#pragma unroll
        for (int e = 0; e < 8; e++) {
            // fold 1/sqrt(HD) AND log2(e): scores emerge in base-2 domain
            qknQ[e] = sqkn[e] * (0.35355339059327373f * 1.4426950408889634f);
            qknK[e] = sqkn[8 + e];
        }
        float csA[4], snA[4], csB[4], snB[4];
        if (TEMPORAL) {
            const float th[4] = {1.f, 0.1f, 0.01f, 0.001f};
#pragma unroll
            for (int j = 0; j < 4; j++) {
                __sincosf((float)tokA * th[j], &snA[j], &csA[j]);
                __sincosf((float)tokB * th[j], &snB[j], &csB[j]);
            }
        }

        u64 hA[16], hB[16];
        {
            u64 x2[16];
            ld_row16(x2, gxA);
            float rs = rsqrtf(sumsq16(x2) * 0.03125f + 1e-6f);
            u64 rs2 = pack2(rs, rs);
            const ulonglong2* nw = (const ulonglong2*)snorm;
#pragma unroll
            for (int i = 0; i < 8; i++) {
                ulonglong2 n = nw[i];
                hA[2 * i] = mul2(mul2(x2[2 * i], rs2), n.x);
                hA[2 * i + 1] = mul2(mul2(x2[2 * i + 1], rs2), n.y);
            }
            ld_row16(x2, gxB);
            rs = rsqrtf(sumsq16(x2) * 0.03125f + 1e-6f);
            rs2 = pack2(rs, rs);
#pragma unroll
            for (int i = 0; i < 8; i++) {
                ulonglong2 n = nw[i];
                hB[2 * i] = mul2(mul2(x2[2 * i], rs2), n.x);
                hB[2 * i + 1] = mul2(mul2(x2[2 * i + 1], rs2), n.y);
            }
        }

        // ---- K heads ----
#pragma unroll 1
        for (int hh = 0; hh < 4; hh++) {
            float aA[8], aB[8];
#pragma unroll
            for (int e = 0; e < 8; e++) {
                float2 d = dot32x2(swk + (hh * 8 + e) * 32, hA, hB);
                aA[e] = d.x; aB[e] = d.y;
            }
            float msA = 0, msB = 0;
#pragma unroll
            for (int e = 0; e < 8; e++) { msA = fmaf(aA[e], aA[e], msA); msB = fmaf(aB[e], aB[e], msB); }
            float scA = rsqrtf(msA * 0.125f + 1e-6f);
            float scB = rsqrtf(msB * 0.125f + 1e-6f);
#pragma unroll
            for (int e = 0; e < 8; e++) { aA[e] *= scA * qknK[e]; aB[e] *= scB * qknK[e]; }
            if (TEMPORAL) {
#pragma unroll
                for (int e = 0; e < 4; e++) {
                    float t0 = aA[e], t1 = aA[e + 4];
                    aA[e] = t0 * csA[e] - t1 * snA[e];
                    aA[e + 4] = fmaf(t0, snA[e], t1 * csA[e]);
                    t0 = aB[e]; t1 = aB[e + 4];
                    aB[e] = t0 * csB[e] - t1 * snB[e];
                    aB[e + 4] = fmaf(t0, snB[e], t1 * csB[e]);
                }
            }
            float* dA = kb + tokA * ROW + hh * 8;
            *(float4*)dA = make_float4(aA[0], aA[1], aA[2], aA[3]);
            *(float4*)(dA + 4) = make_float4(aA[4], aA[5], aA[6], aA[7]);
            if (vB) {
                float* dB = kb + tokB * ROW + hh * 8;
                *(float4*)dB = make_float4(aB[0], aB[1], aB[2], aB[3]);
                *(float4*)(dB + 4) = make_float4(aB[4], aB[5], aB[6], aB[7]);
            }
        }

        // ---- V heads ----
#pragma unroll 1
        for (int hh = 0; hh < 4; hh++) {
            float aA[8], aB[8];
#pragma unroll
            for (int e = 0; e < 8; e++) {
                float2 d = dot32x2(swv + (hh * 8 + e) * 32, hA, hB);
                aA[e] = d.x; aB[e] = d.y;
            }
            float* dA = vb + tokA * ROW + hh * 8;
            *(float4*)dA = make_float4(aA[0], aA[1], aA[2], aA[3]);
            *(float4*)(dA + 4) = make_float4(aA[4], aA[5], aA[6], aA[7]);
            if (vB) {
                float* dB = vb + tokB * ROW + hh * 8;
                *(float4*)dB = make_float4(aB[0], aB[1], aB[2], aB[3]);
                *(float4*)(dB + 4) = make_float4(aB[4], aB[5], aB[6], aB[7]);
            }
        }

        // ---- Q heads ----
#pragma unroll
        for (int hh = 0; hh < 4; hh++) {
            float aA[8], aB[8];
#pragma unroll
            for (int e = 0; e < 8; e++) {
                float2 d = dot32x2(swq + (hh * 8 + e) * 32, hA, hB);
                aA[e] = d.x; aB[e] = d.y;
            }
            float msA = 0, msB = 0;
#pragma unroll
            for (int e = 0; e < 8; e++) { msA = fmaf(aA[e], aA[e], msA); msB = fmaf(aB[e], aB[e], msB); }
            float scA = rsqrtf(msA * 0.125f + 1e-6f);
            float scB = rsqrtf(msB * 0.125f + 1e-6f);
#pragma unroll
            for (int e = 0; e < 8; e++) { aA[e] *= scA * qknQ[e]; aB[e] *= scB * qknQ[e]; }
            if (TEMPORAL) {
#pragma unroll
                for (int e = 0; e < 4; e++) {
                    float t0 = aA[e], t1 = aA[e + 4];
                    aA[e] = t0 * csA[e] - t1 * snA[e];
                    aA[e + 4] = fmaf(t0, snA[e], t1 * csA[e]);
                    t0 = aB[e]; t1 = aB[e + 4];
                    aB[e] = t0 * csB[e] - t1 * snB[e];
                    aB[e + 4] = fmaf(t0, snB[e], t1 * csB[e]);
                }
            }
#pragma unroll
            for (int j = 0; j < 4; j++) {
                qA[4 * hh + j] = pack2(aA[2 * j], aA[2 * j + 1]);
                qB[4 * hh + j] = pack2(aB[2 * j], aB[2 * j + 1]);
            }
        }
    }
    __syncthreads();

    // ================= Phase C: streaming attention (base-2 softmax) =======
    u64 oA[16], oB[16];
    float lA[4], lB[4];
    if (vA) {
#pragma unroll
        for (int i = 0; i < 16; i++) { oA[i] = 0ULL; oB[i] = 0ULL; }
#pragma unroll
        for (int h = 0; h < 4; h++) { lA[h] = 0.f; lB[h] = 0.f; }

#pragma unroll 2
        for (int j = 0; j < S; j++) {
            u64 k2[16], v2[16];
            ld_row16(k2, kb + j * ROW);
            ld_row16(v2, vb + j * ROW);
            float pA[4], pB[4];
#pragma unroll
            for (int hh = 0; hh < 4; hh++) {
                u64 cA = fma2(qA[4 * hh + 1], k2[4 * hh + 1], mul2(qA[4 * hh], k2[4 * hh]));
                u64 dA = fma2(qA[4 * hh + 3], k2[4 * hh + 3], mul2(qA[4 * hh + 2], k2[4 * hh + 2]));
                pA[hh] = ex2f(hsum2(add2(cA, dA)));
                lA[hh] += pA[hh];
                u64 cB = fma2(qB[4 * hh + 1], k2[4 * hh + 1], mul2(qB[4 * hh], k2[4 * hh]));
                u64 dB = fma2(qB[4 * hh + 3], k2[4 * hh + 3], mul2(qB[4 * hh + 2], k2[4 * hh + 2]));
                pB[hh] = ex2f(hsum2(add2(cB, dB)));
                lB[hh] += pB[hh];
            }
#pragma unroll
            for (int hh = 0; hh < 4; hh++) {
                u64 ppA = pack2(pA[hh], pA[hh]);
                u64 ppB = pack2(pB[hh], pB[hh]);
#pragma unroll
                for (int i = 0; i < 4; i++) {
                    oA[4 * hh + i] = fma2(ppA, v2[4 * hh + i], oA[4 * hh + i]);
                    oB[4 * hh + i] = fma2(ppB, v2[4 * hh + i], oB[4 * hh + i]);
                }
            }
        }
#pragma unroll
        for (int hh = 0; hh < 4; hh++) {
            u64 liA = pack2(__fdividef(1.f, lA[hh]), __fdividef(1.f, lA[hh]));
            u64 liB = pack2(__fdividef(1.f, lB[hh]), __fdividef(1.f, lB[hh]));
#pragma unroll
            for (int i = 0; i < 4; i++) {
                oA[4 * hh + i] = mul2(oA[4 * hh + i], liA);
                oB[4 * hh + i] = mul2(oB[4 * hh + i], liB);
            }
        }
    }
    __syncthreads();   // all warps done reading k/v -> k-area reusable for xn

    // ================= Phase D: Wo + residual + FFN + residual =============
    if (vA) {
        float owA[32], owB[32];
        float ssA = 0.f, ssB = 0.f;
#pragma unroll
        for (int d = 0; d < 32; d++) {
            float2 r = dot32x2(swo + d * 32, oA, oB);
            owA[d] = r.x; owB[d] = r.y;
            ssA = fmaf(r.x, r.x, ssA);
            ssB = fmaf(r.y, r.y, ssB);
        }
        u64 rsA = pack2(rsqrtf(ssA * 0.03125f + 1e-6f), rsqrtf(ssA * 0.03125f + 1e-6f));
        u64 rsB = pack2(rsqrtf(ssB * 0.03125f + 1e-6f), rsqrtf(ssB * 0.03125f + 1e-6f));

        u64 h2A[16], h2B[16];
        {
            u64 x2[16], xn[16];
            const ulonglong2* nw1 = (const ulonglong2*)(snorm + 32);
            ld_row16(x2, gxA);
#pragma unroll
            for (int i = 0; i < 8; i++) {
                ulonglong2 n = nw1[i];
                xn[2 * i] = fma2(mul2(pack2(owA[4 * i], owA[4 * i + 1]), rsA), n.x, x2[2 * i]);
                xn[2 * i + 1] = fma2(mul2(pack2(owA[4 * i + 2], owA[4 * i + 3]), rsA), n.y, x2[2 * i + 1]);
            }
            {
                ulonglong2* xo = (ulonglong2*)(kb + tokA * ROW);
#pragma unroll
                for (int i = 0; i < 8; i++) { ulonglong2 t; t.x = xn[2 * i]; t.y = xn[2 * i + 1]; xo[i] = t; }
            }
            float rs = rsqrtf(sumsq16(xn) * 0.03125f + 1e-6f);
            u64 rs2 = pack2(rs, rs);
            const ulonglong2* nw2 = (const ulonglong2*)(snorm + 64);
#pragma unroll
            for (int i = 0; i < 8; i++) {
                ulonglong2 n = nw2[i];
                h2A[2 * i] = mul2(mul2(xn[2 * i], rs2), n.x);
                h2A[2 * i + 1] = mul2(mul2(xn[2 * i + 1], rs2), n.y);
            }
            // token B
            ld_row16(x2, gxB);
#pragma unroll
            for (int i = 0; i < 8; i++) {
                ulonglong2 n = nw1[i];
                xn[2 * i] = fma2(mul2(pack2(owB[4 * i], owB[4 * i + 1]), rsB), n.x, x2[2 * i]);
                xn[2 * i + 1] = fma2(mul2(pack2(owB[4 * i + 2], owB[4 * i + 3]), rsB), n.y, x2[2 * i + 1]);
            }
            if (vB) {
                ulonglong2* xo = (ulonglong2*)(kb + tokB * ROW);
#pragma unroll
                for (int i = 0; i < 8; i++) { ulonglong2 t; t.x = xn[2 * i]; t.y = xn[2 * i + 1]; xo[i] = t; }
            }
            rs = rsqrtf(sumsq16(xn) * 0.03125f + 1e-6f);
            rs2 = pack2(rs, rs);
#pragma unroll
            for (int i = 0; i < 8; i++) {
                ulonglong2 n = nw2[i];
                h2B[2 * i] = mul2(mul2(xn[2 * i], rs2), n.x);
                h2B[2 * i + 1] = mul2(mul2(xn[2 * i + 1], rs2), n.y);
            }
        }

        // ---- FFN ----
        u64 ovA[16], ovB[16];
#pragma unroll
        for (int i = 0; i < 16; i++) { ovA[i] = 0ULL; ovB[i] = 0ULL; }

#pragma unroll 1
        for (int fg = 0; fg < 16; fg++) {
#pragma unroll
            for (int e = 0; e < 4; e++) {
                int f = fg * 4 + e;
                float2 g2 = dot32x2(swg + f * 32, h2A, h2B);
                float2 u2 = dot32x2(swu + f * 32, h2A, h2B);
                float fvA = __fdividef(g2.x, 1.f + __expf(-g2.x)) * u2.x;
                float fvB = __fdividef(g2.y, 1.f + __expf(-g2.y)) * u2.y;
                u64 fA = pack2(fvA, fvA), fB = pack2(fvB, fvB);
                const ulonglong2* wr = (const ulonglong2*)(swout + f * 32);
#pragma unroll
                for (int i = 0; i < 8; i++) {
                    ulonglong2 t = wr[i];
                    ovA[2 * i] = fma2(fA, t.x, ovA[2 * i]);
                    ovA[2 * i + 1] = fma2(fA, t.y, ovA[2 * i + 1]);
                    ovB[2 * i] = fma2(fB, t.x, ovB[2 * i]);
                    ovB[2 * i + 1] = fma2(fB, t.y, ovB[2 * i + 1]);
                }
            }
        }

        // ---- out = xn + rmsnorm(ov), reload xn from k-area, store gmem ----
        {
            const ulonglong2* nw = (const ulonglong2*)(snorm + 96);
            float rs3 = rsqrtf(sumsq16(ovA) * 0.03125f + 1e-6f);
            u64 rs32 = pack2(rs3, rs3);
            u64 xn[16];
            ld_row16(xn, kb + tokA * ROW);
            ulonglong2* go = (ulonglong2*)gxA;
#pragma unroll
            for (int i = 0; i < 8; i++) {
                ulonglong2 n = nw[i];
                ulonglong2 r;
                r.x = fma2(mul2(ovA[2 * i], rs32), n.x, xn[2 * i]);
                r.y = fma2(mul2(ovA[2 * i + 1], rs32), n.y, xn[2 * i + 1]);
                go[i] = r;
            }
            if (vB) {
                rs3 = rsqrtf(sumsq16(ovB) * 0.03125f + 1e-6f);
                rs32 = pack2(rs3, rs3);
                ld_row16(xn, kb + tokB * ROW);
                go = (ulonglong2*)gxB;
#pragma unroll
                for (int i = 0; i < 8; i++) {
                    ulonglong2 n = nw[i];
                    ulonglong2 r;
                    r.x = fma2(mul2(ovB[2 * i], rs32), n.x, xn[2 * i]);
                    r.y = fma2(mul2(ovB[2 * i + 1], rs32), n.y, xn[2 * i + 1]);
                    go[i] = r;
                }
            }
        }
    }
}

// ---------------------------------------------------------------------------
// Final: rmsnorm + extract 3 CLS tokens of last timestep.
// ---------------------------------------------------------------------------
__global__ void final_kernel(const float* __restrict__ fnorm, float* __restrict__ out) {
    int b = blockIdx.x / 3, k = blockIdx.x % 3, lane = threadIdx.x;
    float x = g_tokens[(((long)b * 128 + 127) * 67 + 64 + k) * 32 + lane];
    float ms = warp_sum(x * x) * (1.f / 32.f);
    out[(k * 16 + b) * 32 + lane] = x * rsqrtf(ms + 1e-6f) * fnorm[lane];
}

// ---------------------------------------------------------------------------
// Launch
// ---------------------------------------------------------------------------
extern "C" void kernel_launch(void* const* d_in, const int* in_sizes, int n_in,
                              void* d_out, int out_size) {
    const float* obs    = (const float*)d_in[0];
    const float* Wval   = (const float*)d_in[1];
    const float* bval   = (const float*)d_in[2];
    const float* innorm = (const float*)d_in[3];
    const float* dimemb = (const float*)d_in[4];
    const float* cls    = (const float*)d_in[5];
    const float* fnorm  = (const float*)d_in[6];
    const float* sWq   = (const float*)d_in[7];
    const float* sWk   = (const float*)d_in[8];
    const float* sWv   = (const float*)d_in[9];
    const float* sWo   = (const float*)d_in[10];
    const float* sWg   = (const float*)d_in[11];
    const float* sWu   = (const float*)d_in[12];
    const float* sWout = (const float*)d_in[13];
    const float* sN4   = (const float*)d_in[14];
    const float* sQKN  = (const float*)d_in[15];
    const float* tWq   = (const float*)d_in[16];
    const float* tWk   = (const float*)d_in[17];
    const float* tWv   = (const float*)d_in[18];
    const float* tWo   = (const float*)d_in[19];
    const float* tWg   = (const float*)d_in[20];
    const float* tWu   = (const float*)d_in[21];
    const float* tWout = (const float*)d_in[22];
    const float* tN4   = (const float*)d_in[23];
    const float* tQKN  = (const float*)d_in[24];

    // smem floats: NSEQ*2*S*36 + 10240 + 144
    const int SZ_S = (3 * 2 * 67 * 36 + 10240 + 144) * 4;    // 99424
    const int SZ_T = (4 * 2 * 128 * 36 + 10240 + 144) * 4;   // 188992

    cudaFuncSetAttribute(attn_tpl<67, 3, false>, cudaFuncAttributeMaxDynamicSharedMemorySize, SZ_S);
    cudaFuncSetAttribute(attn_tpl<128, 4, true>, cudaFuncAttributeMaxDynamicSharedMemorySize, SZ_T);

    embed_kernel<<<2048, 256>>>(obs, Wval, bval, innorm, dimemb, cls);

    const int GRID_S = (2048 + 2) / 3;   // 683
    const int GRID_T = 1072 / 4;         // 268

    for (int layer = 0; layer < 3; layer++) {
        attn_tpl<67, 3, false><<<GRID_S, 128, SZ_S>>>(
            sWq + layer * 1024, sWk + layer * 1024, sWv + layer * 1024, sWo + layer * 1024,
            sWg + layer * 2048, sWu + layer * 2048, sWout + layer * 2048,
            sN4 + layer * 128, sQKN + layer * 16, 2048);
        if (layer < 2) {
            attn_tpl<128, 4, true><<<GRID_T, 256, SZ_T>>>(
                tWq + layer * 1024, tWk + layer * 1024, tWv + layer * 1024, tWo + layer * 1024,
                tWg + layer * 2048, tWu + layer * 2048, tWout + layer * 2048,
                tN4 + layer * 128, tQKN + layer * 16, 1072);
        }
    }

    final_kernel<<<48, 32>>>(fnorm, (float*)d_out);
}